// round 2
// baseline (speedup 1.0000x reference)
#include <cuda_runtime.h>
#include <cstdint>

// ---------------------------------------------------------------------------
// PolyGIoULoss: per-pair rotated-box GIoU loss, weighted mean over N pairs.
// One thread = one box pair. Two-stage deterministic reduction.
// ---------------------------------------------------------------------------

#define NBMAX 4096
__device__ float g_partial[NBMAX];

// Exact replica of reference sorted_poly_area via angular-successor walk.
// vm: validity bitmask for points [0, P).
template <int P>
__device__ __forceinline__ float sorted_poly_area(const float* px, const float* py, unsigned vm) {
    // masked mean (matches (pts*maskf).sum / max(cnt,1))
    float cnt = 0.f, sx = 0.f, sy = 0.f;
#pragma unroll
    for (int i = 0; i < P; i++) {
        float mf = ((vm >> i) & 1u) ? 1.f : 0.f;
        cnt += mf;
        sx += px[i] * mf;
        sy += py[i] * mf;
    }
    float num = fmaxf(cnt, 1.f);
    float mx = sx / num;
    float my = sy / num;

    // sortable keys: monotone pseudo-angle bits (31:5) | index (4:0); invalid = all-ones
    unsigned long long key[P];
#pragma unroll
    for (int i = 0; i < P; i++) {
        float cx = px[i] - mx;
        float cy = py[i] - my;
        float den = fabsf(cx) + fabsf(cy);
        den = (den == 0.f) ? 1.f : den;
        // diamond pseudo-angle in [-2,2], monotone in atan2(cy,cx)
        float pa = copysignf(1.f - __fdividef(cx, den), cy);
        int ib = __float_as_int(pa);
        unsigned u = (unsigned)(ib ^ ((ib >> 31) | 0x80000000));
        key[i] = ((vm >> i) & 1u)
                     ? ((((unsigned long long)u) << 5) | (unsigned long long)i)
                     : ~0ull;
    }

    // global minimum-key valid point (wrap target)
    unsigned long long kmin = ~0ull;
    float gx = 0.f, gy = 0.f;
#pragma unroll
    for (int i = 0; i < P; i++) {
        bool p = key[i] < kmin;
        kmin = p ? key[i] : kmin;
        gx = p ? px[i] : gx;
        gy = p ? py[i] : gy;
    }

    // shoelace over angular-successor chain
    float s = 0.f;
#pragma unroll
    for (int i = 0; i < P; i++) {
        unsigned long long ki = key[i];
        unsigned long long bk = ~0ull;
        float bx = gx, by = gy;  // default: wrap to min-key point
#pragma unroll
        for (int j = 0; j < P; j++) {
            bool p = (key[j] > ki) && (key[j] < bk);
            bk = p ? key[j] : bk;
            bx = p ? px[j] : bx;
            by = p ? py[j] : by;
        }
        float mf = ((vm >> i) & 1u) ? 1.f : 0.f;
        s += (px[i] * by - py[i] * bx) * mf;
    }
    return fabsf(s) * 0.5f;
}

__global__ void poly_giou_kernel(const float* __restrict__ pred,
                                 const float* __restrict__ target,
                                 const float* __restrict__ weight,
                                 int N) {
    const float dxc[4] = {0.5f, -0.5f, -0.5f, 0.5f};
    const float dyc[4] = {0.5f, 0.5f, -0.5f, -0.5f};

    float acc = 0.f;
    int stride = gridDim.x * blockDim.x;
    for (int idx = blockIdx.x * blockDim.x + threadIdx.x; idx < N; idx += stride) {
        float p0 = pred[5 * idx + 0], p1 = pred[5 * idx + 1];
        float p2 = pred[5 * idx + 2], p3 = pred[5 * idx + 3], p4 = pred[5 * idx + 4];
        float t0 = target[5 * idx + 0], t1 = target[5 * idx + 1];
        float t2 = target[5 * idx + 2], t3 = target[5 * idx + 3], t4 = target[5 * idx + 4];

        float pts_x[24], pts_y[24];

        // box2corners for pred -> pts[0..3], target -> pts[4..7]
        float s1, c1;
        sincosf(p4, &s1, &c1);
        float s2, c2;
        sincosf(t4, &s2, &c2);
#pragma unroll
        for (int k = 0; k < 4; k++) {
            float cx = dxc[k] * p2, cy = dyc[k] * p3;
            pts_x[k] = cx * c1 - cy * s1 + p0;
            pts_y[k] = cx * s1 + cy * c1 + p1;
            float cx2 = dxc[k] * t2, cy2 = dyc[k] * t3;
            pts_x[4 + k] = cx2 * c2 - cy2 * s2 + t0;
            pts_y[4 + k] = cx2 * s2 + cy2 * c2 + t1;
        }

        unsigned vm = 0;

        // box_intersections: edge i of box1 vs edge j of box2 -> slot 8 + i*4 + j
#pragma unroll
        for (int i = 0; i < 4; i++) {
            float x1 = pts_x[i], y1 = pts_y[i];
            float x2 = pts_x[(i + 1) & 3], y2 = pts_y[(i + 1) & 3];
            float dxa = x2 - x1, dya = y2 - y1;
#pragma unroll
            for (int j = 0; j < 4; j++) {
                float x3 = pts_x[4 + j], y3 = pts_y[4 + j];
                float x4 = pts_x[4 + ((j + 1) & 3)], y4 = pts_y[4 + ((j + 1) & 3)];
                float dxb = x4 - x3, dyb = y4 - y3;
                float den = dxa * dyb - dya * dxb;
                float dens = (den == 0.f) ? 1.f : den;
                float t = ((x3 - x1) * dyb - (y3 - y1) * dxb) / dens;
                float u = ((x3 - x1) * dya - (y3 - y1) * dxa) / dens;
                bool m = (den != 0.f) && (t > 0.f) && (t < 1.f) && (u > 0.f) && (u < 1.f);
                float mf = m ? 1.f : 0.f;
                int slot = 8 + i * 4 + j;
                pts_x[slot] = (x1 + t * dxa) * mf;
                pts_y[slot] = (y1 + t * dya) * mf;
                vm |= (m ? 1u : 0u) << slot;
            }
        }

        // corners_in_box(c1, c2): corners of box1 inside box2 -> bits 0..3
        {
            float ax = pts_x[4], ay = pts_y[4];
            float abx = pts_x[5] - ax, aby = pts_y[5] - ay;
            float adx = pts_x[7] - ax, ady = pts_y[7] - ay;
            float abab = abx * abx + aby * aby;
            float adad = adx * adx + ady * ady;
#pragma unroll
            for (int k = 0; k < 4; k++) {
                float amx = pts_x[k] - ax, amy = pts_y[k] - ay;
                float pab = (amx * abx + amy * aby) / abab;
                float pad = (amx * adx + amy * ady) / adad;
                bool m = (pab > -1e-6f) && (pab < (1.0f + 1e-6f)) &&
                         (pad > -1e-6f) && (pad < (1.0f + 1e-6f));
                vm |= (m ? 1u : 0u) << k;
            }
        }
        // corners_in_box(c2, c1): corners of box2 inside box1 -> bits 4..7
        {
            float ax = pts_x[0], ay = pts_y[0];
            float abx = pts_x[1] - ax, aby = pts_y[1] - ay;
            float adx = pts_x[3] - ax, ady = pts_y[3] - ay;
            float abab = abx * abx + aby * aby;
            float adad = adx * adx + ady * ady;
#pragma unroll
            for (int k = 0; k < 4; k++) {
                float amx = pts_x[4 + k] - ax, amy = pts_y[4 + k] - ay;
                float pab = (amx * abx + amy * aby) / abab;
                float pad = (amx * adx + amy * ady) / adad;
                bool m = (pab > -1e-6f) && (pab < (1.0f + 1e-6f)) &&
                         (pad > -1e-6f) && (pad < (1.0f + 1e-6f));
                vm |= (m ? 1u : 0u) << (4 + k);
            }
        }

        float overlap = sorted_poly_area<24>(pts_x, pts_y, vm);

        float area1 = p2 * p3;
        float area2 = t2 * t3;
        float uni = area1 + area2 - overlap + 1e-6f;
        float iou = fmaxf(overlap / uni, 1e-6f);

        float enclose = sorted_poly_area<8>(pts_x, pts_y, 0xFFu);

        float giou = iou - (enclose - uni) / enclose;
        float loss = 1.f - giou;
        acc += loss * weight[idx];
    }

    // block reduction (deterministic)
    float v = acc;
#pragma unroll
    for (int o = 16; o > 0; o >>= 1) v += __shfl_down_sync(0xFFFFFFFFu, v, o);
    __shared__ float ws[8];
    int lane = threadIdx.x & 31;
    int wid = threadIdx.x >> 5;
    if (lane == 0) ws[wid] = v;
    __syncthreads();
    if (wid == 0) {
        int nw = (blockDim.x + 31) >> 5;
        float t = (lane < nw) ? ws[lane] : 0.f;
#pragma unroll
        for (int o = 4; o > 0; o >>= 1) t += __shfl_down_sync(0xFFFFFFFFu, t, o);
        if (lane == 0) g_partial[blockIdx.x] = t;
    }
}

__global__ void reduce_partials(float* out, int nblocks, int N) {
    __shared__ double sh[256];
    double s = 0.0;
    for (int i = threadIdx.x; i < nblocks; i += blockDim.x) s += (double)g_partial[i];
    sh[threadIdx.x] = s;
    __syncthreads();
    for (int o = 128; o > 0; o >>= 1) {
        if (threadIdx.x < o) sh[threadIdx.x] += sh[threadIdx.x + o];
        __syncthreads();
    }
    if (threadIdx.x == 0) out[0] = (float)(sh[0] / (double)N);
}

extern "C" void kernel_launch(void* const* d_in, const int* in_sizes, int n_in,
                              void* d_out, int out_size) {
    const float* pred = (const float*)d_in[0];
    const float* target = (const float*)d_in[1];
    const float* weight = (const float*)d_in[2];
    int N = in_sizes[2];  // weight has N elements

    int threads = 256;
    int blocks = (N + threads - 1) / threads;
    if (blocks > NBMAX) blocks = NBMAX;

    poly_giou_kernel<<<blocks, threads>>>(pred, target, weight, N);
    reduce_partials<<<1, 256>>>((float*)d_out, blocks, N);
}

// round 3
// speedup vs baseline: 6.9315x; 6.9315x over previous
#include <cuda_runtime.h>
#include <cstdint>

#define NBMAX 8192
__device__ float g_partial[NBMAX];

// monotone-in-atan2 sortable key: (pseudo-angle bits & ~31) | index. invalid -> 0xFFFFFFE0|i
__device__ __forceinline__ unsigned angle_key(float cx, float cy, int i, bool valid) {
    float den = fabsf(cx) + fabsf(cy);
    den = (den == 0.f) ? 1.f : den;
    float pa = copysignf(1.f - __fdividef(cx, den), cy);  // diamond angle in [-2,2]
    int ib = __float_as_int(pa);
    unsigned u = (unsigned)(ib ^ ((ib >> 31) | 0x80000000));
    return valid ? ((u & 0xFFFFFFE0u) | (unsigned)i) : (0xFFFFFFE0u | (unsigned)i);
}

template <int NN>
__device__ __forceinline__ void bitonic_sort(unsigned (&key)[NN]) {
#pragma unroll
    for (int k = 2; k <= NN; k <<= 1)
#pragma unroll
        for (int j = k >> 1; j > 0; j >>= 1)
#pragma unroll
            for (int i = 0; i < NN; i++) {
                int l = i ^ j;
                if (l > i) {
                    unsigned a = key[i], b = key[l];
                    unsigned lo = min(a, b), hi = max(a, b);
                    if ((i & k) == 0) { key[i] = lo; key[l] = hi; }
                    else              { key[i] = hi; key[l] = lo; }
                }
            }
}

// shoelace over angular-sorted keys; invalid keys (>= 0xFFFFFFE0) wrap to first point.
// Matches reference: invalid sorted slots duplicate sp[:,0:1] (zero contribution).
template <int NN, int MAXV>
__device__ __forceinline__ float sorted_shoelace(const unsigned (&key)[NN], const float2* lp) {
    const unsigned INV = 0xFFFFFFE0u;
    float2 v0 = lp[key[0] & 31u];
    float cx = v0.x, cy = v0.y;
    float s = 0.f;
#pragma unroll
    for (int i = 0; i < MAXV; i++) {
        bool vi = key[i] < INV;
        unsigned nk = (i + 1 < NN) ? key[i + 1] : 0xFFFFFFFFu;
        bool vn = nk < INV;
        float2 nb = lp[nk & 31u];
        float nx = vn ? nb.x : v0.x;
        float ny = vn ? nb.y : v0.y;
        s += vi ? (cx * ny - cy * nx) : 0.f;
        cx = nx; cy = ny;
    }
    return fabsf(s) * 0.5f;
}

__global__ void __launch_bounds__(256) poly_giou_kernel(const float* __restrict__ pred,
                                                        const float* __restrict__ target,
                                                        const float* __restrict__ weight,
                                                        int N) {
    const float dxc[4] = {0.5f, -0.5f, -0.5f, 0.5f};
    const float dyc[4] = {0.5f, 0.5f, -0.5f, -0.5f};

    float acc = 0.f;
    int stride = gridDim.x * blockDim.x;
    for (int idx = blockIdx.x * blockDim.x + threadIdx.x; idx < N; idx += stride) {
        float p0 = pred[5 * idx + 0], p1 = pred[5 * idx + 1];
        float p2 = pred[5 * idx + 2], p3 = pred[5 * idx + 3], p4 = pred[5 * idx + 4];
        float t0 = target[5 * idx + 0], t1 = target[5 * idx + 1];
        float t2 = target[5 * idx + 2], t3 = target[5 * idx + 3], t4 = target[5 * idx + 4];

        float2 lp[32];  // 24 candidate points + 8 zero pads (local mem, gathered dynamically)
#pragma unroll
        for (int i = 24; i < 32; i++) lp[i] = make_float2(0.f, 0.f);

        float s1, c1, s2, c2;
        __sincosf(p4, &s1, &c1);
        __sincosf(t4, &s2, &c2);

        float c1x[4], c1y[4], c2x[4], c2y[4];
#pragma unroll
        for (int k = 0; k < 4; k++) {
            float cx = dxc[k] * p2, cy = dyc[k] * p3;
            c1x[k] = cx * c1 - cy * s1 + p0;
            c1y[k] = cx * s1 + cy * c1 + p1;
            float cx2 = dxc[k] * t2, cy2 = dyc[k] * t3;
            c2x[k] = cx2 * c2 - cy2 * s2 + t0;
            c2y[k] = cx2 * s2 + cy2 * c2 + t1;
            lp[k] = make_float2(c1x[k], c1y[k]);
            lp[4 + k] = make_float2(c2x[k], c2y[k]);
        }

        unsigned vm = 0;
        float cnt = 0.f, sx = 0.f, sy = 0.f;

        // corners of box1 inside box2 -> bits 0..3
        {
            float ax = c2x[0], ay = c2y[0];
            float abx = c2x[1] - ax, aby = c2y[1] - ay;
            float adx = c2x[3] - ax, ady = c2y[3] - ay;
            float iab = __fdividef(1.f, abx * abx + aby * aby);
            float iad = __fdividef(1.f, adx * adx + ady * ady);
#pragma unroll
            for (int k = 0; k < 4; k++) {
                float amx = c1x[k] - ax, amy = c1y[k] - ay;
                float pab = (amx * abx + amy * aby) * iab;
                float pad = (amx * adx + amy * ady) * iad;
                bool m = (pab > -1e-6f) && (pab < 1.000001f) && (pad > -1e-6f) && (pad < 1.000001f);
                vm |= (m ? 1u : 0u) << k;
                float mf = m ? 1.f : 0.f;
                cnt += mf; sx += c1x[k] * mf; sy += c1y[k] * mf;
            }
        }
        // corners of box2 inside box1 -> bits 4..7
        {
            float ax = c1x[0], ay = c1y[0];
            float abx = c1x[1] - ax, aby = c1y[1] - ay;
            float adx = c1x[3] - ax, ady = c1y[3] - ay;
            float iab = __fdividef(1.f, abx * abx + aby * aby);
            float iad = __fdividef(1.f, adx * adx + ady * ady);
#pragma unroll
            for (int k = 0; k < 4; k++) {
                float amx = c2x[k] - ax, amy = c2y[k] - ay;
                float pab = (amx * abx + amy * aby) * iab;
                float pad = (amx * adx + amy * ady) * iad;
                bool m = (pab > -1e-6f) && (pab < 1.000001f) && (pad > -1e-6f) && (pad < 1.000001f);
                vm |= (m ? 1u : 0u) << (4 + k);
                float mf = m ? 1.f : 0.f;
                cnt += mf; sx += c2x[k] * mf; sy += c2y[k] * mf;
            }
        }

        // edge-edge intersections -> slots 8 + i*4 + j
#pragma unroll
        for (int i = 0; i < 4; i++) {
            float x1 = c1x[i], y1 = c1y[i];
            float dxa = c1x[(i + 1) & 3] - x1, dya = c1y[(i + 1) & 3] - y1;
#pragma unroll
            for (int j = 0; j < 4; j++) {
                float x3 = c2x[j], y3 = c2y[j];
                float dxb = c2x[(j + 1) & 3] - x3, dyb = c2y[(j + 1) & 3] - y3;
                float den = dxa * dyb - dya * dxb;
                float idens = __fdividef(1.f, (den == 0.f) ? 1.f : den);
                float t = ((x3 - x1) * dyb - (y3 - y1) * dxb) * idens;
                float u = ((x3 - x1) * dya - (y3 - y1) * dxa) * idens;
                bool m = (den != 0.f) && (t > 0.f) && (t < 1.f) && (u > 0.f) && (u < 1.f);
                float mf = m ? 1.f : 0.f;
                float px = (x1 + t * dxa) * mf;
                float py = (y1 + t * dya) * mf;
                int slot = 8 + i * 4 + j;
                lp[slot] = make_float2(px, py);
                vm |= (m ? 1u : 0u) << slot;
                cnt += mf; sx += px; sy += py;
            }
        }

        // ---- overlap: angular sort of valid points + shoelace ----
        float overlap;
        {
            float invn = __fdividef(1.f, fmaxf(cnt, 1.f));
            float mx = sx * invn, my = sy * invn;
            unsigned key[32];
#pragma unroll
            for (int i = 0; i < 4; i++) key[i] = angle_key(c1x[i] - mx, c1y[i] - my, i, (vm >> i) & 1u);
#pragma unroll
            for (int i = 0; i < 4; i++) key[4 + i] = angle_key(c2x[i] - mx, c2y[i] - my, 4 + i, (vm >> (4 + i)) & 1u);
#pragma unroll
            for (int i = 8; i < 24; i++) {
                float2 p = lp[i];
                key[i] = angle_key(p.x - mx, p.y - my, i, (vm >> i) & 1u);
            }
#pragma unroll
            for (int i = 24; i < 32; i++) key[i] = 0xFFFFFFFFu;
            bitonic_sort<32>(key);
            overlap = sorted_shoelace<32, 24>(key, lp);
        }

        // ---- enclose: angular sort of all 8 corners + shoelace ----
        float enclose;
        {
            float emx = (c1x[0] + c1x[1] + c1x[2] + c1x[3] + c2x[0] + c2x[1] + c2x[2] + c2x[3]) * 0.125f;
            float emy = (c1y[0] + c1y[1] + c1y[2] + c1y[3] + c2y[0] + c2y[1] + c2y[2] + c2y[3]) * 0.125f;
            unsigned ek[8];
#pragma unroll
            for (int i = 0; i < 4; i++) ek[i] = angle_key(c1x[i] - emx, c1y[i] - emy, i, true);
#pragma unroll
            for (int i = 0; i < 4; i++) ek[4 + i] = angle_key(c2x[i] - emx, c2y[i] - emy, 4 + i, true);
            bitonic_sort<8>(ek);
            enclose = sorted_shoelace<8, 8>(ek, lp);
        }

        float area1 = p2 * p3;
        float area2 = t2 * t3;
        float uni = area1 + area2 - overlap + 1e-6f;
        float iou = fmaxf(__fdividef(overlap, uni), 1e-6f);
        float giou = iou - __fdividef(enclose - uni, enclose);
        acc += (1.f - giou) * weight[idx];
    }

    // deterministic block reduction
    float v = acc;
#pragma unroll
    for (int o = 16; o > 0; o >>= 1) v += __shfl_down_sync(0xFFFFFFFFu, v, o);
    __shared__ float ws[8];
    int lane = threadIdx.x & 31;
    int wid = threadIdx.x >> 5;
    if (lane == 0) ws[wid] = v;
    __syncthreads();
    if (wid == 0) {
        int nw = (blockDim.x + 31) >> 5;
        float t = (lane < nw) ? ws[lane] : 0.f;
#pragma unroll
        for (int o = 4; o > 0; o >>= 1) t += __shfl_down_sync(0xFFFFFFFFu, t, o);
        if (lane == 0) g_partial[blockIdx.x] = t;
    }
}

__global__ void reduce_partials(float* out, int nblocks, int N) {
    __shared__ double sh[256];
    double s = 0.0;
    for (int i = threadIdx.x; i < nblocks; i += blockDim.x) s += (double)g_partial[i];
    sh[threadIdx.x] = s;
    __syncthreads();
    for (int o = 128; o > 0; o >>= 1) {
        if (threadIdx.x < o) sh[threadIdx.x] += sh[threadIdx.x + o];
        __syncthreads();
    }
    if (threadIdx.x == 0) out[0] = (float)(sh[0] / (double)N);
}

extern "C" void kernel_launch(void* const* d_in, const int* in_sizes, int n_in,
                              void* d_out, int out_size) {
    const float* pred = (const float*)d_in[0];
    const float* target = (const float*)d_in[1];
    const float* weight = (const float*)d_in[2];
    int N = in_sizes[2];

    int threads = 256;
    int blocks = (N + threads - 1) / threads;
    if (blocks > NBMAX) blocks = NBMAX;

    poly_giou_kernel<<<blocks, threads>>>(pred, target, weight, N);
    reduce_partials<<<1, 256>>>((float*)d_out, blocks, N);
}